// round 5
// baseline (speedup 1.0000x reference)
#include <cuda_runtime.h>
#include <cstdint>

#define TSTEPS  1024
#define FEAT    64
#define UNITS   256
#define FOURU   1024
#define KQ      64       // K rows per k-quarter (K = 256 now, h only)
#define NCOLS   128      // gate-columns per CTA: 32 units x 4 gates
#define ASTR    36       // padded floats per h row
#define CLUSTER 8
#define RTHREADS 512
#define BB      32       // batch rows per cluster
#define NCLUST  16
#define HBUF_F  (UNITS * ASTR)          // 9216 floats per h buffer
#define HBUF_B  (HBUF_F * 4)            // 36864 bytes
#define EXPECT_BYTES (CLUSTER * RTHREADS * 8)   // 32768 B per inbox phase

// z_x scratch: zx[t][b][c], c = unit*4 + gate, bias folded in. Split into two
// 1 GB arrays (t<512 / t>=512) to stay under 2^31-byte object limits.
__device__ float g_zxA[(size_t)512 * 512 * 1024];
__device__ float g_zxB[(size_t)512 * 512 * 1024];

// ---------- packed f32x2 helpers ----------
__device__ __forceinline__ unsigned long long pk2(float lo, float hi) {
    unsigned long long r;
    asm("mov.b64 %0, {%1, %2};" : "=l"(r) : "f"(lo), "f"(hi));
    return r;
}
__device__ __forceinline__ void fma2(unsigned long long& d,
                                     unsigned long long a,
                                     unsigned long long b) {
    asm("fma.rn.f32x2 %0, %1, %2, %0;" : "+l"(d) : "l"(a), "l"(b));
}
__device__ __forceinline__ float2 up2(unsigned long long v) {
    float2 r;
    asm("mov.b64 {%0, %1}, %2;" : "=f"(r.x), "=f"(r.y) : "l"(v));
    return r;
}
__device__ __forceinline__ unsigned long long xadd(unsigned long long v, int m) {
    uint32_t lo, hi;
    asm("mov.b64 {%0,%1}, %2;" : "=r"(lo), "=r"(hi) : "l"(v));
    lo = __shfl_xor_sync(0xffffffffu, lo, m);
    hi = __shfl_xor_sync(0xffffffffu, hi, m);
    unsigned long long o;
    asm("mov.b64 %0, {%1,%2};" : "=l"(o) : "r"(lo), "r"(hi));
    asm("add.rn.f32x2 %0, %0, %1;" : "+l"(v) : "l"(o));
    return v;
}

__device__ __forceinline__ float fsig(float x) {
    return __fdividef(1.0f, 1.0f + __expf(-x));
}
__device__ __forceinline__ float ftanh(float x) {
    return fmaf(2.0f, fsig(2.0f * x), -1.0f);
}

// mbarrier wait (parity, acquire cluster-scope so peer DSMEM stores are visible)
__device__ __forceinline__ void mbar_wait(uint32_t mbar, uint32_t parity) {
    uint32_t done;
    do {
        asm volatile(
            "{\n\t.reg .pred P;\n\t"
            "mbarrier.try_wait.parity.acquire.cluster.shared::cta.b64 P, [%1], %2, 0x989680;\n\t"
            "selp.b32 %0, 1, 0, P;\n\t}"
            : "=r"(done) : "r"(mbar), "r"(parity) : "memory");
    } while (!done);
}

// ============================================================================
// Kernel 1: z_x[t][b][unit*4+gate] = x[b,t,:] @ W[:, gate*256+unit] + bias
// grid (512 b, 2 col-halves), 512 threads. W half staged in SMEM (128 KB).
// ============================================================================
__global__ void __launch_bounds__(512, 1)
zx_kernel(const float* __restrict__ x, const float* __restrict__ W,
          const float* __restrict__ bias)
{
    extern __shared__ float sm[];
    float* Wsm = sm;              // [64][512]
    float* xs  = sm + 64 * 512;   // [32][64]
    const int tid = threadIdx.x;
    const int b   = blockIdx.x;
    const int ch  = blockIdx.y;

    for (int idx = tid; idx < 64 * 512; idx += 512) {
        const int k = idx >> 9, cl = idx & 511;
        const int gcol = (cl & 3) * UNITS + ch * 128 + (cl >> 2);
        Wsm[idx] = W[(size_t)k * FOURU + gcol];
    }
    const int r2 = tid >> 5;   // row-pair index 0..15 (rows 2r2, 2r2+1 in chunk)
    const int cg = tid & 31;   // 16-col group

    unsigned long long bacc[8];
    #pragma unroll
    for (int j = 0; j < 8; j++) {
        const int g0 = ch * 512 + cg * 16 + 2 * j;
        const float bb0 = bias[(g0 & 3) * UNITS + (g0 >> 2)];
        const int g1 = g0 + 1;
        const float bb1 = bias[(g1 & 3) * UNITS + (g1 >> 2)];
        bacc[j] = pk2(bb0, bb1);
    }

    const float* xb = x + (size_t)b * TSTEPS * FEAT;
    for (int chunk = 0; chunk < 32; chunk++) {
        __syncthreads();
        {
            const int row = tid >> 4, f4 = tid & 15;
            const float4 v = *(const float4*)(xb + (size_t)(chunk * 32 + row) * FEAT + f4 * 4);
            *(float4*)(xs + row * 64 + f4 * 4) = v;
        }
        __syncthreads();

        unsigned long long acc0[8], acc1[8];
        #pragma unroll
        for (int j = 0; j < 8; j++) { acc0[j] = bacc[j]; acc1[j] = bacc[j]; }

        const float* wp = Wsm + cg * 16;
        const float* x0 = xs + (2 * r2) * 64;
        const float* x1 = x0 + 64;
        #pragma unroll 4
        for (int k = 0; k < 64; k++) {
            const float4 w0 = *(const float4*)(wp + k * 512 + 0);
            const float4 w1 = *(const float4*)(wp + k * 512 + 4);
            const float4 w2 = *(const float4*)(wp + k * 512 + 8);
            const float4 w3 = *(const float4*)(wp + k * 512 + 12);
            unsigned long long wv[8] = { pk2(w0.x, w0.y), pk2(w0.z, w0.w),
                                         pk2(w1.x, w1.y), pk2(w1.z, w1.w),
                                         pk2(w2.x, w2.y), pk2(w2.z, w2.w),
                                         pk2(w3.x, w3.y), pk2(w3.z, w3.w) };
            const unsigned long long a0 = pk2(x0[k], x0[k]);
            const unsigned long long a1 = pk2(x1[k], x1[k]);
            #pragma unroll
            for (int j = 0; j < 8; j++) { fma2(acc0[j], a0, wv[j]); fma2(acc1[j], a1, wv[j]); }
        }

        const int t0 = chunk * 32 + 2 * r2;          // even; t0 and t0+1 same half
        float* zbase = (t0 < 512) ? g_zxA : g_zxB;
        const int tt = t0 & 511;
        float* o0 = zbase + ((size_t)tt * 512 + b) * FOURU + ch * 512 + cg * 16;
        float* o1 = o0 + (size_t)512 * FOURU;
        #pragma unroll
        for (int j = 0; j < 8; j += 2) {
            const float2 p0 = up2(acc0[j]), p1 = up2(acc0[j + 1]);
            *(float4*)(o0 + j * 2) = make_float4(p0.x, p0.y, p1.x, p1.y);
            const float2 q0 = up2(acc1[j]), q1 = up2(acc1[j + 1]);
            *(float4*)(o1 + j * 2) = make_float4(q0.x, q0.y, q1.x, q1.y);
        }
    }
}

// ============================================================================
// Kernel 2: recurrent LSTM, 16 clusters x 8 CTAs x 512 thr. Uh slice in SMEM,
// double-buffered h exchanged via st.async + per-CTA inbox mbarriers (no
// cluster-wide barrier in the loop). Epilogue: out[b,:] = sigmoid(h_T.dw+db)
// (softmax over size-1 axis == 1, attention row == h_T).
// ============================================================================
extern "C" __global__ void __launch_bounds__(RTHREADS, 1) __cluster_dims__(CLUSTER, 1, 1)
lstm_kernel(const float* __restrict__ Uh, const float* __restrict__ dw,
            const float* __restrict__ db, float* __restrict__ out)
{
    extern __shared__ float smem[];
    float* Uc = smem;                          // [256][128]  131072 B
    float* hb = smem + UNITS * NCOLS;          // h0, h1      2x36864 B

    const int tid = threadIdx.x;
    uint32_t rank, cid;
    asm("mov.u32 %0, %%cluster_ctarank;" : "=r"(rank));
    asm("mov.u32 %0, %%clusterid.x;"     : "=r"(cid));

    uint32_t smem_u32;
    asm("{ .reg .u64 t0; cvta.to.shared.u64 t0, %1; cvt.u32.u64 %0, t0; }"
        : "=r"(smem_u32) : "l"(smem));
    const uint32_t hb_u32    = smem_u32 + UNITS * NCOLS * 4;
    const uint32_t inbox_u32 = hb_u32 + 2 * HBUF_B;    // 2 mbarriers (16 B)

    // ---- init: weights, zero h buffers, mbarriers; one-time cluster sync ----
    for (int idx = tid; idx < UNITS * NCOLS; idx += RTHREADS) {
        const int k = idx >> 7, c = idx & 127;
        const int gcol = (c & 3) * UNITS + (int)rank * 32 + (c >> 2);
        Uc[idx] = Uh[(size_t)k * FOURU + gcol];
    }
    for (int i = tid; i < 2 * HBUF_F; i += RTHREADS) hb[i] = 0.0f;
    if (tid == 0) {
        asm volatile("mbarrier.init.shared.b64 [%0], 1;" :: "r"(inbox_u32)     : "memory");
        asm volatile("mbarrier.init.shared.b64 [%0], 1;" :: "r"(inbox_u32 + 8) : "memory");
    }
    __syncthreads();
    asm volatile("barrier.cluster.arrive.aligned;" ::: "memory");
    asm volatile("barrier.cluster.wait.aligned;"   ::: "memory");

    // ---- thread mapping ----
    const int wid  = tid >> 5, lane = tid & 31;
    const int ugq  = wid & 3;        // unit group (8 units)
    const int bq   = wid >> 2;       // batch group (8 batches)
    const int kq   = lane >> 3;      // K quarter
    const int u8   = lane & 7;
    const int unit = ugq * 8 + u8;   // local unit 0..31

    // remote destination / inbox base addresses (buf0; buf1 = +HBUF_B / +8)
    const uint32_t my_off =
        (uint32_t)(((((int)rank * 32 + unit) * ASTR) + bq * 8 + kq * 2) * 4);
    uint32_t dstb[CLUSTER], mbb[CLUSTER];
    #pragma unroll
    for (int r = 0; r < CLUSTER; r++) {
        asm("mapa.shared::cluster.u32 %0, %1, %2;" : "=r"(dstb[r]) : "r"(hb_u32 + my_off), "r"(r));
        asm("mapa.shared::cluster.u32 %0, %1, %2;" : "=r"(mbb[r])  : "r"(inbox_u32),       "r"(r));
    }

    const int b0 = (int)cid * BB + bq * 8 + kq * 2;          // my 2 global batches
    const int cb = ((int)rank * 32 + unit) * 4;              // my z_x column base
    const float* ucp = Uc + unit * 4 + kq * KQ * NCOLS;

    float cst0 = 0.0f, cst1 = 0.0f;

    // preload z_x(t=0)
    float4 zA = *(const float4*)(g_zxA + (size_t)b0 * FOURU + cb);
    float4 zB = *(const float4*)(g_zxA + (size_t)(b0 + 1) * FOURU + cb);

    for (int t = 0; t < TSTEPS; t++) {
        // receiver posts expect_tx for next phase (inbox[(t+1)&1])
        if (tid == 0) {
            asm volatile("mbarrier.arrive.expect_tx.shared.b64 _, [%0], %1;"
                :: "r"(inbox_u32 + (uint32_t)(((t + 1) & 1) * 8)),
                   "r"((uint32_t)EXPECT_BYTES) : "memory");
        }
        // prefetch z_x(t+1) — issued before the wait, overlaps producer latency
        float4 zAn = zA, zBn = zB;
        if (t < TSTEPS - 1) {
            const int tn = t + 1;
            const float* zp = ((tn < 512) ? g_zxA : g_zxB) +
                              ((size_t)(tn & 511) * 512 + b0) * FOURU + cb;
            zAn = *(const float4*)zp;
            zBn = *(const float4*)(zp + FOURU);
        }
        if (t > 0)
            mbar_wait(inbox_u32 + (uint32_t)((t & 1) * 8),
                      (uint32_t)(((t - 1) >> 1) & 1));

        // ---- z_h = h @ Uc over my K-quarter: 8 batches x 4 gates ----
        unsigned long long acc[4][4];
        #pragma unroll
        for (int p = 0; p < 4; p++)
            #pragma unroll
            for (int g = 0; g < 4; g++) acc[p][g] = 0ull;

        const float* ap = hb + (t & 1) * HBUF_F + bq * 8 + kq * KQ * ASTR;
        #pragma unroll 4
        for (int kk = 0; kk < KQ; kk++) {
            const float4 u4 = *(const float4*)(ucp + kk * NCOLS);
            const float4 a0 = *(const float4*)(ap + kk * ASTR);
            const float4 a1 = *(const float4*)(ap + kk * ASTR + 4);
            unsigned long long ug[4] = { pk2(u4.x, u4.x), pk2(u4.y, u4.y),
                                         pk2(u4.z, u4.z), pk2(u4.w, u4.w) };
            unsigned long long apair[4] = { pk2(a0.x, a0.y), pk2(a0.z, a0.w),
                                            pk2(a1.x, a1.y), pk2(a1.z, a1.w) };
            #pragma unroll
            for (int p = 0; p < 4; p++)
                #pragma unroll
                for (int g = 0; g < 4; g++)
                    fma2(acc[p][g], apair[p], ug[g]);
        }

        // ---- reduce K-quarters across lanes ----
        #pragma unroll
        for (int p = 0; p < 4; p++)
            #pragma unroll
            for (int g = 0; g < 4; g++) {
                acc[p][g] = xadd(acc[p][g], 8);
                acc[p][g] = xadd(acc[p][g], 16);
            }

        // ---- gates for my 2 batches (z_x already includes x@W + bias) ----
        const float2 zi = up2(acc[kq][0]);
        const float2 zf = up2(acc[kq][1]);
        const float2 zg = up2(acc[kq][2]);
        const float2 zo = up2(acc[kq][3]);
        float h0v, h1v;
        {
            const float ig = fsig(zi.x + zA.x), fg = fsig(zf.x + zA.y);
            const float gg = ftanh(zg.x + zA.z), og = fsig(zo.x + zA.w);
            cst0 = fmaf(fg, cst0, ig * gg);
            h0v  = og * ftanh(cst0);
        }
        {
            const float ig = fsig(zi.y + zB.x), fg = fsig(zf.y + zB.y);
            const float gg = ftanh(zg.y + zB.z), og = fsig(zo.y + zB.w);
            cst1 = fmaf(fg, cst1, ig * gg);
            h1v  = og * ftanh(cst1);
        }
        const unsigned long long hv = pk2(h0v, h1v);

        // ---- push h pair to all 8 ranks' buf[(t+1)&1], signal their inbox ----
        const uint32_t doff = (uint32_t)(((t + 1) & 1) * HBUF_B);
        const uint32_t moff = (uint32_t)(((t + 1) & 1) * 8);
        #pragma unroll
        for (int r = 0; r < CLUSTER; r++) {
            asm volatile(
                "st.async.weak.shared::cluster.mbarrier::complete_tx::bytes.b64 [%0], %1, [%2];"
                :: "r"(dstb[r] + doff), "l"(hv), "r"(mbb[r] + moff) : "memory");
        }
        zA = zAn; zB = zBn;
    }

    // final h_T landed in buf[0] (TSTEPS even); wait its phase (parity 1)
    mbar_wait(inbox_u32, (uint32_t)(((TSTEPS - 1) >> 1) & 1));

    // ---- epilogue ----
    {
        const int bl = (int)rank * 4 + (wid & 3);
        float s = 0.0f;
        for (int u = lane; u < UNITS; u += 32)
            s += hb[u * ASTR + bl] * dw[u];
        #pragma unroll
        for (int o = 16; o > 0; o >>= 1)
            s += __shfl_xor_sync(0xffffffffu, s, o);
        const float val = fsig(s + db[0]);
        float* op = out + ((size_t)cid * BB + bl) * TSTEPS + (wid >> 2) * 256;
        for (int i = lane; i < 256; i += 32)
            op[i] = val;
    }
}

extern "C" void kernel_launch(void* const* d_in, const int* in_sizes, int n_in,
                              void* d_out, int out_size)
{
    const float* x  = (const float*)d_in[0];
    const float* W  = (const float*)d_in[1];
    const float* Uh = (const float*)d_in[2];
    const float* b  = (const float*)d_in[3];
    const float* dw = (const float*)d_in[4];
    const float* db = (const float*)d_in[5];
    float* out = (float*)d_out;

    const size_t zxsmem = (size_t)(64 * 512 + 32 * 64) * sizeof(float);
    cudaFuncSetAttribute(zx_kernel,
                         cudaFuncAttributeMaxDynamicSharedMemorySize, (int)zxsmem);
    zx_kernel<<<dim3(512, 2), 512, zxsmem>>>(x, W, b);

    const size_t rsmem = (size_t)(UNITS * NCOLS + 2 * HBUF_F) * sizeof(float) + 32;
    cudaFuncSetAttribute(lstm_kernel,
                         cudaFuncAttributeMaxDynamicSharedMemorySize, (int)rsmem);
    lstm_kernel<<<NCLUST * CLUSTER, RTHREADS, rsmem>>>(Uh, dw, db, out);
}

// round 7
// speedup vs baseline: 1.5849x; 1.5849x over previous
#include <cuda_runtime.h>
#include <cstdint>

#define TSTEPS  1024
#define FEAT    64
#define UNITS   256
#define FOURU   1024
#define KQ      64        // K rows per k-quarter (K = 256, h only)
#define NCOLS   128       // gate-columns per CTA: 32 units x 4 gates
#define CLUSTER 8
#define RTHREADS 256
#define BB      32        // batch rows per cluster
#define NCLUST  16
#define HROW    32        // floats per h row (32 batches)
#define HSKEW   8         // +8 floats per 64-row chunk (bank decorrelation)
#define HBUF_F  (UNITS * HROW + 4 * HSKEW)   // 8224 floats per h buffer
#define SLAB_F  (32 * 32)                    // 1024 floats = 4096 B
#define EXPECT_BYTES (CLUSTER * SLAB_F * 4)  // 32768 B per inbox phase

// z_x scratch: zx[t][b][c], c = unit*4 + gate, bias folded in. Two 1 GB halves.
__device__ float g_zxA[(size_t)512 * 512 * 1024];
__device__ float g_zxB[(size_t)512 * 512 * 1024];

// ---------- packed f32x2 helpers ----------
__device__ __forceinline__ unsigned long long dup2(float x) {
    unsigned long long r; uint32_t u = __float_as_uint(x);
    asm("mov.b64 %0, {%1, %1};" : "=l"(r) : "r"(u));
    return r;
}
__device__ __forceinline__ void fma2(unsigned long long& d,
                                     unsigned long long a,
                                     unsigned long long b) {
    asm("fma.rn.f32x2 %0, %1, %2, %0;" : "+l"(d) : "l"(a), "l"(b));
}
__device__ __forceinline__ float2 up2(unsigned long long v) {
    float2 r;
    asm("mov.b64 {%0, %1}, %2;" : "=f"(r.x), "=f"(r.y) : "l"(v));
    return r;
}
__device__ __forceinline__ unsigned long long xadd(unsigned long long v, int m) {
    uint32_t lo, hi;
    asm("mov.b64 {%0,%1}, %2;" : "=r"(lo), "=r"(hi) : "l"(v));
    lo = __shfl_xor_sync(0xffffffffu, lo, m);
    hi = __shfl_xor_sync(0xffffffffu, hi, m);
    unsigned long long o;
    asm("mov.b64 %0, {%1,%2};" : "=l"(o) : "r"(lo), "r"(hi));
    asm("add.rn.f32x2 %0, %0, %1;" : "+l"(v) : "l"(o));
    return v;
}

__device__ __forceinline__ float fsig(float x) {
    return __fdividef(1.0f, 1.0f + __expf(-x));
}
__device__ __forceinline__ float ftanh(float x) {
    return fmaf(2.0f, fsig(2.0f * x), -1.0f);
}

__device__ __forceinline__ void mbar_wait(uint32_t mbar, uint32_t parity) {
    uint32_t done;
    do {
        asm volatile(
            "{\n\t.reg .pred P;\n\t"
            "mbarrier.try_wait.parity.acquire.cluster.shared::cta.b64 P, [%1], %2, 0x989680;\n\t"
            "selp.b32 %0, 1, 0, P;\n\t}"
            : "=r"(done) : "r"(mbar), "r"(parity) : "memory");
    } while (!done);
}

// ============================================================================
// Kernel 1: zx[t][b][unit*4+gate] = x[b,t,:] @ W(perm) + bias(perm)
// grid (4 col-chunks, 512 b); block 256 thr loops 16 t-tiles of 64.
// ============================================================================
__global__ void __launch_bounds__(256)
zx_kernel(const float* __restrict__ x, const float* __restrict__ W,
          const float* __restrict__ bias)
{
    extern __shared__ float sm[];
    float* Wt = sm;                 // [64][256]  65536 B
    float* xt = sm + 64 * 256;      // [64][68]   17408 B (k-major, padded)

    const int tid = threadIdx.x;
    const int ch  = blockIdx.x;     // 256-col chunk (0..3)
    const int b   = blockIdx.y;     // batch (0..511)

    for (int idx = tid; idx < 64 * 256; idx += 256) {
        const int k = idx >> 8, cc = idx & 255;
        const int gcol = (cc & 3) * UNITS + ch * 64 + (cc >> 2);
        Wt[idx] = W[(size_t)k * FOURU + gcol];
    }

    const int tg = tid >> 4;        // t-group (4 rows)
    const int cg = tid & 15;        // col-group (16 cols)

    unsigned long long bp[8];
    #pragma unroll
    for (int j = 0; j < 8; j++) {
        const int c0 = cg * 16 + 2 * j;
        const int g0 = (c0 & 3) * UNITS + ch * 64 + (c0 >> 2);
        const int c1 = c0 + 1;
        const int g1 = (c1 & 3) * UNITS + ch * 64 + (c1 >> 2);
        unsigned long long r;
        uint32_t lo = __float_as_uint(bias[g0]), hi = __float_as_uint(bias[g1]);
        asm("mov.b64 %0, {%1,%2};" : "=l"(r) : "r"(lo), "r"(hi));
        bp[j] = r;
    }

    const float* xb = x + (size_t)b * TSTEPS * FEAT;

    for (int tb = 0; tb < 16; tb++) {
        __syncthreads();
        for (int it = 0; it < 4; it++) {
            const int idx = tid + it * 256;          // 0..1023
            const int tt  = idx & 63;
            const int k4  = idx >> 6;                // 0..15
            const float4 v = *(const float4*)(xb + (size_t)(tb * 64 + tt) * FEAT + k4 * 4);
            xt[(k4 * 4 + 0) * 68 + tt] = v.x;
            xt[(k4 * 4 + 1) * 68 + tt] = v.y;
            xt[(k4 * 4 + 2) * 68 + tt] = v.z;
            xt[(k4 * 4 + 3) * 68 + tt] = v.w;
        }
        __syncthreads();

        unsigned long long acc[4][8];
        #pragma unroll
        for (int i = 0; i < 4; i++)
            #pragma unroll
            for (int j = 0; j < 8; j++) acc[i][j] = bp[j];

        const float* xp = xt + tg * 4;
        const ulonglong2* wp = (const ulonglong2*)(Wt + cg * 16);
        #pragma unroll 4
        for (int k = 0; k < 64; k++) {
            const float4 xv = *(const float4*)(xp + k * 68);
            unsigned long long xd[4] = { dup2(xv.x), dup2(xv.y), dup2(xv.z), dup2(xv.w) };
            // Wt row = 256 floats = 64 ulonglong2 (FIX: was k*16)
            const ulonglong2 w0 = wp[k * 64 + 0];
            const ulonglong2 w1 = wp[k * 64 + 1];
            const ulonglong2 w2 = wp[k * 64 + 2];
            const ulonglong2 w3 = wp[k * 64 + 3];
            const unsigned long long wv[8] = { w0.x, w0.y, w1.x, w1.y,
                                               w2.x, w2.y, w3.x, w3.y };
            #pragma unroll
            for (int i = 0; i < 4; i++)
                #pragma unroll
                for (int j = 0; j < 8; j++)
                    fma2(acc[i][j], xd[i], wv[j]);
        }

        #pragma unroll
        for (int i = 0; i < 4; i++) {
            const int t = tb * 64 + tg * 4 + i;
            float* zb = ((t < 512) ? g_zxA : g_zxB) +
                        ((size_t)(t & 511) * 512 + b) * FOURU + ch * 256 + cg * 16;
            #pragma unroll
            for (int j = 0; j < 8; j += 2) {
                const float2 p0 = up2(acc[i][j]), p1 = up2(acc[i][j + 1]);
                *(float4*)(zb + j * 2) = make_float4(p0.x, p0.y, p1.x, p1.y);
            }
        }
    }
}

// ============================================================================
// Kernel 2: recurrent LSTM. 16 clusters x 8 CTAs x 256 thr. Uh slice in SMEM.
// Thread: 16 batches x 4 gates, f32x2 batch-pairs, K-quarter lane split.
// h exchanged via slab + 8 cp.async.bulk per CTA/step into double-buffered,
// bank-skewed h buffers. Epilogue uses softmax-over-size-1-axis collapse.
// ============================================================================
extern "C" __global__ void __launch_bounds__(RTHREADS, 1) __cluster_dims__(CLUSTER, 1, 1)
lstm_kernel(const float* __restrict__ Uh, const float* __restrict__ dw,
            const float* __restrict__ db, float* __restrict__ out)
{
    extern __shared__ float smem[];
    float* Uc   = smem;                              // [256][128] 131072 B
    float* hb   = smem + UNITS * NCOLS;              // 2 x 8224 floats
    float* slab = hb + 2 * HBUF_F;                   // 2 x 1024 floats

    const int tid = threadIdx.x;
    uint32_t rank, cid;
    asm("mov.u32 %0, %%cluster_ctarank;" : "=r"(rank));
    asm("mov.u32 %0, %%clusterid.x;"     : "=r"(cid));

    uint32_t smem_u32;
    asm("{ .reg .u64 t0; cvta.to.shared.u64 t0, %1; cvt.u32.u64 %0, t0; }"
        : "=r"(smem_u32) : "l"(smem));
    const uint32_t hb_u32    = smem_u32 + UNITS * NCOLS * 4;
    const uint32_t slab_u32  = hb_u32 + 2 * HBUF_F * 4;
    const uint32_t inbox_u32 = slab_u32 + 2 * SLAB_F * 4;   // 2 mbarriers

    for (int idx = tid; idx < UNITS * NCOLS; idx += RTHREADS) {
        const int k = idx >> 7, c = idx & 127;
        const int gcol = (c & 3) * UNITS + (int)rank * 32 + (c >> 2);
        Uc[idx] = Uh[(size_t)k * FOURU + gcol];
    }
    for (int i = tid; i < 2 * HBUF_F; i += RTHREADS) hb[i] = 0.0f;
    if (tid == 0) {
        asm volatile("mbarrier.init.shared.b64 [%0], 1;" :: "r"(inbox_u32)     : "memory");
        asm volatile("mbarrier.init.shared.b64 [%0], 1;" :: "r"(inbox_u32 + 8) : "memory");
    }
    __syncthreads();
    asm volatile("barrier.cluster.arrive.aligned;" ::: "memory");
    asm volatile("barrier.cluster.wait.aligned;"   ::: "memory");

    const int wid  = tid >> 5, lane = tid & 31;
    const int ugq  = wid & 3;        // unit group (8 units)
    const int bq   = wid >> 2;       // batch half (16 batches)
    const int kq   = lane >> 3;      // K quarter
    const int u8   = lane & 7;
    const int unit = ugq * 8 + u8;   // local unit 0..31

    uint32_t dstb[CLUSTER], mbb[CLUSTER];
    {
        const uint32_t my_hoff = (uint32_t)(((int)rank * 1024 + ((int)rank >> 1) * HSKEW) * 4);
        #pragma unroll
        for (int r = 0; r < CLUSTER; r++) {
            asm("mapa.shared::cluster.u32 %0, %1, %2;" : "=r"(dstb[r]) : "r"(hb_u32 + my_hoff), "r"(r));
            asm("mapa.shared::cluster.u32 %0, %1, %2;" : "=r"(mbb[r])  : "r"(inbox_u32),        "r"(r));
        }
    }

    const int bloc = bq * 16 + kq * 4;                        // my 4 batches (local)
    const int b0   = (int)cid * BB + bloc;                    // global
    const int cb   = ((int)rank * 32 + unit) * 4;             // zx column base

    const float4* ucp = (const float4*)(Uc + unit * 4 + (kq * KQ) * NCOLS);
    const ulonglong2* apb = (const ulonglong2*)(hb + (kq * KQ) * HROW + kq * HSKEW + bq * 16);

    float cst[4] = {0.f, 0.f, 0.f, 0.f};

    float4 zc[4];
    #pragma unroll
    for (int j = 0; j < 4; j++)
        zc[j] = *(const float4*)(g_zxA + (size_t)(b0 + j) * FOURU + cb);

    for (int t = 0; t < TSTEPS; t++) {
        if (tid == 0) {
            asm volatile("mbarrier.arrive.expect_tx.shared.b64 _, [%0], %1;"
                :: "r"(inbox_u32 + (uint32_t)(((t + 1) & 1) * 8)),
                   "r"((uint32_t)EXPECT_BYTES) : "memory");
        }
        float4 zn[4];
        #pragma unroll
        for (int j = 0; j < 4; j++) zn[j] = zc[j];
        if (t < TSTEPS - 1) {
            const int tn = t + 1;
            const float* zp = ((tn < 512) ? g_zxA : g_zxB) +
                              ((size_t)(tn & 511) * 512 + b0) * FOURU + cb;
            #pragma unroll
            for (int j = 0; j < 4; j++) zn[j] = *(const float4*)(zp + (size_t)j * FOURU);
        }
        if (t > 0)
            mbar_wait(inbox_u32 + (uint32_t)((t & 1) * 8),
                      (uint32_t)(((t - 1) >> 1) & 1));

        unsigned long long acc[8][4];
        #pragma unroll
        for (int p = 0; p < 8; p++)
            #pragma unroll
            for (int g = 0; g < 4; g++) acc[p][g] = 0ull;

        const ulonglong2* ap = (const ulonglong2*)((const char*)apb +
                               (size_t)(t & 1) * (HBUF_F * 4));
        #pragma unroll 4
        for (int kk = 0; kk < KQ; kk++) {
            const float4 u4 = ucp[kk * 32];
            const unsigned long long ug[4] = { dup2(u4.x), dup2(u4.y),
                                               dup2(u4.z), dup2(u4.w) };
            // hb row = HROW(32) floats = 8 ulonglong2 (FIX: was kk*4)
            const ulonglong2 a0 = ap[kk * 8 + 0];
            const ulonglong2 a1 = ap[kk * 8 + 1];
            const ulonglong2 a2 = ap[kk * 8 + 2];
            const ulonglong2 a3 = ap[kk * 8 + 3];
            const unsigned long long av[8] = { a0.x, a0.y, a1.x, a1.y,
                                               a2.x, a2.y, a3.x, a3.y };
            #pragma unroll
            for (int p = 0; p < 8; p++)
                #pragma unroll
                for (int g = 0; g < 4; g++)
                    fma2(acc[p][g], av[p], ug[g]);
        }

        #pragma unroll
        for (int p = 0; p < 8; p++)
            #pragma unroll
            for (int g = 0; g < 4; g++) {
                acc[p][g] = xadd(acc[p][g], 8);
                acc[p][g] = xadd(acc[p][g], 16);
            }

        const bool m1 = (kq >= 2), m0 = (kq & 1);
        unsigned long long zA[4], zB[4];
        #pragma unroll
        for (int g = 0; g < 4; g++) {
            const unsigned long long s0 = m1 ? acc[4][g] : acc[0][g];
            const unsigned long long s1 = m1 ? acc[5][g] : acc[1][g];
            const unsigned long long s2 = m1 ? acc[6][g] : acc[2][g];
            const unsigned long long s3 = m1 ? acc[7][g] : acc[3][g];
            zA[g] = m0 ? s2 : s0;
            zB[g] = m0 ? s3 : s1;
        }

        float hh[4];
        #pragma unroll
        for (int pr = 0; pr < 2; pr++) {
            const float2 zi = up2(pr ? zB[0] : zA[0]);
            const float2 zf = up2(pr ? zB[1] : zA[1]);
            const float2 zg = up2(pr ? zB[2] : zA[2]);
            const float2 zo = up2(pr ? zB[3] : zA[3]);
            {
                const int j = 2 * pr;
                const float ig = fsig(zi.x + zc[j].x), fg = fsig(zf.x + zc[j].y);
                const float gg = ftanh(zg.x + zc[j].z), og = fsig(zo.x + zc[j].w);
                cst[j] = fmaf(fg, cst[j], ig * gg);
                hh[j]  = og * ftanh(cst[j]);
            }
            {
                const int j = 2 * pr + 1;
                const float ig = fsig(zi.y + zc[j].x), fg = fsig(zf.y + zc[j].y);
                const float gg = ftanh(zg.y + zc[j].z), og = fsig(zo.y + zc[j].w);
                cst[j] = fmaf(fg, cst[j], ig * gg);
                hh[j]  = og * ftanh(cst[j]);
            }
        }

        *(float4*)(slab + ((t + 1) & 1) * SLAB_F + unit * 32 + bloc) =
            make_float4(hh[0], hh[1], hh[2], hh[3]);
        __syncthreads();
        if (tid == 0) {
            asm volatile("fence.proxy.async.shared::cta;" ::: "memory");
            const uint32_t src  = slab_u32 + (uint32_t)(((t + 1) & 1) * SLAB_F * 4);
            const uint32_t doff = (uint32_t)(((t + 1) & 1) * HBUF_F * 4);
            const uint32_t moff = (uint32_t)(((t + 1) & 1) * 8);
            #pragma unroll
            for (int r = 0; r < CLUSTER; r++) {
                asm volatile(
                    "cp.async.bulk.shared::cluster.shared::cta.mbarrier::complete_tx::bytes "
                    "[%0], [%1], %2, [%3];"
                    :: "r"(dstb[r] + doff), "r"(src), "r"((uint32_t)(SLAB_F * 4)),
                       "r"(mbb[r] + moff) : "memory");
            }
        }
        #pragma unroll
        for (int j = 0; j < 4; j++) zc[j] = zn[j];
    }

    mbar_wait(inbox_u32, (uint32_t)(((TSTEPS - 1) >> 1) & 1));
    asm volatile("barrier.cluster.arrive.aligned;" ::: "memory");

    {
        const int bl = (int)rank * 4 + (wid & 3);     // local batch 0..31
        float s = 0.0f;
        for (int u = lane; u < UNITS; u += 32)
            s += hb[u * HROW + (u >> 6) * HSKEW + bl] * dw[u];
        #pragma unroll
        for (int o = 16; o > 0; o >>= 1)
            s += __shfl_xor_sync(0xffffffffu, s, o);
        const float val = fsig(s + db[0]);
        float* op = out + ((size_t)cid * BB + bl) * TSTEPS + (wid >> 2) * 512;
        for (int i = lane; i < 512; i += 32)
            op[i] = val;
    }
    asm volatile("barrier.cluster.wait.aligned;" ::: "memory");
}

extern "C" void kernel_launch(void* const* d_in, const int* in_sizes, int n_in,
                              void* d_out, int out_size)
{
    const float* x  = (const float*)d_in[0];
    const float* W  = (const float*)d_in[1];
    const float* Uh = (const float*)d_in[2];
    const float* b  = (const float*)d_in[3];
    const float* dw = (const float*)d_in[4];
    const float* db = (const float*)d_in[5];
    float* out = (float*)d_out;

    const size_t zsm = (size_t)(64 * 256 + 64 * 68) * sizeof(float);
    cudaFuncSetAttribute(zx_kernel,
                         cudaFuncAttributeMaxDynamicSharedMemorySize, (int)zsm);
    zx_kernel<<<dim3(4, 512), 256, zsm>>>(x, W, b);

    const size_t rsm = (size_t)(UNITS * NCOLS + 2 * HBUF_F + 2 * SLAB_F) * sizeof(float) + 32;
    cudaFuncSetAttribute(lstm_kernel,
                         cudaFuncAttributeMaxDynamicSharedMemorySize, (int)rsm);
    lstm_kernel<<<NCLUST * CLUSTER, RTHREADS, rsm>>>(Uh, dw, db, out);
}